// round 15
// baseline (speedup 1.0000x reference)
#include <cuda_runtime.h>
#include <cuda_fp16.h>

#define FULLMASK 0xffffffffu

constexpr int MAXN = 50016;
constexpr int MAXE = 1000000;
constexpr int MAXB = 256;          // max scan blocks (N/256)

// ---------------- scratch (static device memory: allocation-free) -------------
__device__ float  g_h1[MAXN * 64];   // layer1 pre-agg features fp32 (N,4,16)
__device__ float  g_act1[MAXN * 64]; // layer1 output after bias+ELU (fp32)
__device__ __half g_h2[MAXN * 40];   // layer2 pre-agg features, fp16
__device__ float g_as1[MAXN * 4];
__device__ float g_ad1[MAXN * 4];
__device__ float g_as2[MAXN];
__device__ float g_ad2[MAXN];
__device__ int   g_deg[MAXN];
__device__ int   g_off[MAXN + 1];
__device__ int   g_csr[MAXE];        // source node ids grouped by dst
__device__ int   g_rank[MAXE];       // within-destination rank of each edge
__device__ int           g_partial[MAXB];
__device__ volatile int  g_flag[MAXB];

// ---------------- fused GEMM1 (+coef1 epilogue) || count+rank -----------------
// GEMM uses k-major transposed x tile (pad 68) so the hot loop is
// 2x LDS.128 + 16 FFMA per k.
__global__ void gemm1_count_kernel(const float* __restrict__ x,
                                   const float* __restrict__ W,
                                   const float* __restrict__ a_s,
                                   const float* __restrict__ a_d,
                                   const int* __restrict__ ei,
                                   float* __restrict__ out,
                                   int N, int E, int G1, int CB) {
    __shared__ float xs[64 * 68];    // transposed [k][row], pad 68 (17KB)
    __shared__ float Ws[64 * 64];    // 16KB
    int tid = threadIdx.x;

    if ((int)blockIdx.x >= G1) {     // ---- count + rank path (grid-stride) ----
        int stride = CB * 256;
        for (int e = (blockIdx.x - G1) * 256 + tid; e < E; e += stride) {
            int d = __ldg(&ei[E + e]);
            if ((unsigned)d < (unsigned)N)
                g_rank[e] = atomicAdd(&g_deg[d], 1);
        }
        return;
    }

    // ---- gemm path ----
    int base = blockIdx.x * 64;
    int ty = tid >> 4, tx = tid & 15;
    float acc[4][4] = {};
    const float4* xg = (const float4*)x;
    const float4* Wg = (const float4*)W;
    #pragma unroll
    for (int kc = 0; kc < 2; kc++) {
        for (int i = tid; i < 1024; i += 256) {      // 64 rows x 16 float4
            int r = i >> 4, c = i & 15;
            int row = base + r;
            float4 val = (row < N) ? xg[row * 32 + kc * 16 + c]
                                   : make_float4(0.f, 0.f, 0.f, 0.f);
            xs[(4 * c + 0) * 68 + r] = val.x;
            xs[(4 * c + 1) * 68 + r] = val.y;
            xs[(4 * c + 2) * 68 + r] = val.z;
            xs[(4 * c + 3) * 68 + r] = val.w;
        }
        for (int i = tid; i < 1024; i += 256) {
            int r = i >> 4, c = i & 15;
            ((float4*)Ws)[i] = Wg[(kc * 64 + r) * 16 + c];
        }
        __syncthreads();
        #pragma unroll 8
        for (int k = 0; k < 64; k++) {
            float4 wv = ((float4*)Ws)[k * 16 + tx];
            float4 xv = *(const float4*)&xs[k * 68 + ty * 4];
            acc[0][0] += xv.x * wv.x; acc[0][1] += xv.x * wv.y;
            acc[0][2] += xv.x * wv.z; acc[0][3] += xv.x * wv.w;
            acc[1][0] += xv.y * wv.x; acc[1][1] += xv.y * wv.y;
            acc[1][2] += xv.y * wv.z; acc[1][3] += xv.y * wv.w;
            acc[2][0] += xv.z * wv.x; acc[2][1] += xv.z * wv.y;
            acc[2][2] += xv.z * wv.z; acc[2][3] += xv.z * wv.w;
            acc[3][0] += xv.w * wv.x; acc[3][1] += xv.w * wv.y;
            acc[3][2] += xv.w * wv.z; acc[3][3] += xv.w * wv.w;
        }
        __syncthreads();
    }
    #pragma unroll
    for (int i = 0; i < 4; i++) {
        int row = base + ty * 4 + i;
        if (row < N)
            *(float4*)(out + row * 64 + tx * 4) =
                make_float4(acc[i][0], acc[i][1], acc[i][2], acc[i][3]);
    }

    // ---- coef1 epilogue (fp32): head h = tx>>2 owns cols tx*4..tx*4+3
    float asc[4], adc[4];
    #pragma unroll
    for (int j = 0; j < 4; j++) {
        asc[j] = __ldg(a_s + tx * 4 + j);
        adc[j] = __ldg(a_d + tx * 4 + j);
    }
    int h = tx >> 2;
    #pragma unroll
    for (int i = 0; i < 4; i++) {
        float s1 = acc[i][0] * asc[0] + acc[i][1] * asc[1]
                 + acc[i][2] * asc[2] + acc[i][3] * asc[3];
        float s2 = acc[i][0] * adc[0] + acc[i][1] * adc[1]
                 + acc[i][2] * adc[2] + acc[i][3] * adc[3];
        s1 += __shfl_xor_sync(FULLMASK, s1, 1);
        s1 += __shfl_xor_sync(FULLMASK, s1, 2);
        s2 += __shfl_xor_sync(FULLMASK, s2, 1);
        s2 += __shfl_xor_sync(FULLMASK, s2, 2);
        int row = base + ty * 4 + i;
        if ((tx & 3) == 0 && row < N) {
            g_as1[row * 4 + h] = s1;
            g_ad1[row * 4 + h] = s2;
        }
    }
}

// ---------------- single-kernel decoupled-lookback scan ----------------------
__global__ void scan_kernel_lb(int N, int E) {
    int b = blockIdx.x, tid = threadIdx.x, lane = tid & 31, wid = tid >> 5;
    int i = b * 256 + tid;
    int x = (i < N) ? g_deg[i] : 0;
    int v = x;
    #pragma unroll
    for (int d = 1; d < 32; d <<= 1) {
        int t = __shfl_up_sync(FULLMASK, v, d);
        if (lane >= d) v += t;
    }
    __shared__ int ws[8];
    __shared__ int s_prev;
    if (lane == 31) ws[wid] = v;
    if (tid == 0) s_prev = 0;
    __syncthreads();
    if (tid < 8) {
        int wv = ws[tid];
        #pragma unroll
        for (int d = 1; d < 8; d <<= 1) {
            int t = __shfl_up_sync(0xffu, wv, d);
            if (tid >= d) wv += t;
        }
        ws[tid] = wv;   // inclusive warp totals
    }
    __syncthreads();
    int incl = v + ((wid == 0) ? 0 : ws[wid - 1]);
    if (tid == 0) {
        g_partial[b] = ws[7];
        __threadfence();
        g_flag[b] = 1;
    }
    if (tid < b) {
        while (g_flag[tid] == 0) { }
        __threadfence();
        atomicAdd(&s_prev, g_partial[tid]);
    }
    __syncthreads();
    int excl = s_prev + incl - x;
    if (i < N) g_off[i] = excl;
    if (b == 0 && tid == 0) g_off[N] = E;
}

// ---------------- atomic-free scatter, 8 edges/thread (MLP=8) ----------------
__global__ void scatter_kernel(const int* __restrict__ ei, int E, int N) {
    int b0 = blockIdx.x * 2048;
    #pragma unroll
    for (int k = 0; k < 8; k++) {
        int e = b0 + k * 256 + threadIdx.x;
        if (e < E) {
            int s = __ldg(&ei[e]);
            int d = __ldg(&ei[E + e]);
            if ((unsigned)s < (unsigned)N && (unsigned)d < (unsigned)N)
                g_csr[__ldg(&g_off[d]) + g_rank[e]] = s;
        }
    }
}

// ---------------- GEMM 2 (+coef2 epilogue): act1[N,64]@W2[64,40], half out ---
__global__ void gemm2_kernel(const float* __restrict__ x, const float* __restrict__ W,
                             const float* __restrict__ a_s, const float* __restrict__ a_d,
                             __half* __restrict__ out, int N) {
    __shared__ float xs[64 * 64];    // 16KB
    __shared__ float Ws[64 * 40];    // 10KB
    int tid = threadIdx.x;
    int base = blockIdx.x * 64;
    const float4* xg = (const float4*)x;
    for (int i = tid; i < 1024; i += 128) {
        int r = i >> 4, c = i & 15;
        int row = base + r;
        ((float4*)xs)[i] = (row < N) ? xg[row * 16 + c]
                                     : make_float4(0.f, 0.f, 0.f, 0.f);
    }
    for (int i = tid; i < 640; i += 128)
        ((float4*)Ws)[i] = ((const float4*)W)[i];
    __syncthreads();
    int ty = tid >> 3, tx = tid & 7;                 // 16 row-groups x 8 col-groups
    int c0 = tx * 5;
    float acc[4][5] = {};
    #pragma unroll 4
    for (int k = 0; k < 64; k++) {
        float wv[5];
        #pragma unroll
        for (int j = 0; j < 5; j++) wv[j] = Ws[k * 40 + c0 + j];
        #pragma unroll
        for (int i = 0; i < 4; i++) {
            float xv = xs[(ty * 4 + i) * 64 + k];
            #pragma unroll
            for (int j = 0; j < 5; j++) acc[i][j] += xv * wv[j];
        }
    }
    float asc[5], adc[5];
    #pragma unroll
    for (int j = 0; j < 5; j++) {
        asc[j] = __ldg(a_s + c0 + j);
        adc[j] = __ldg(a_d + c0 + j);
    }
    #pragma unroll
    for (int i = 0; i < 4; i++) {
        int row = base + ty * 4 + i;
        if (row < N) {
            #pragma unroll
            for (int j = 0; j < 5; j++)
                out[row * 40 + c0 + j] = __float2half_rn(acc[i][j]);
        }
        float s1 = 0.f, s2 = 0.f;
        #pragma unroll
        for (int j = 0; j < 5; j++) { s1 += acc[i][j] * asc[j]; s2 += acc[i][j] * adc[j]; }
        #pragma unroll
        for (int d = 1; d < 8; d <<= 1) {
            s1 += __shfl_xor_sync(FULLMASK, s1, d);
            s2 += __shfl_xor_sync(FULLMASK, s2, d);
        }
        if (tx == 0 && row < N) { g_as2[row] = s1; g_ad2[row] = s2; }
    }
}

// ---------------- layer-1 aggregate: H=4, C=16, fp32 gather, +bias+ELU -------
// 4 edges per warp-iteration, 8 lanes per edge, each lane loads 8 floats
// (2x LDG.128) and accumulates fp32. No converts. Partials via xor-8/16.
__global__ void gat_agg1(const float* __restrict__ hf,
                         const float* __restrict__ as,
                         const float* __restrict__ ad,
                         const float* __restrict__ bias,
                         float* __restrict__ out, int N) {
    __shared__ float smw[4][128];           // 4 warps x 32 edges x 4 heads
    int warp = (blockIdx.x * blockDim.x + threadIdx.x) >> 5;
    int lane = threadIdx.x & 31;
    int wl = threadIdx.x >> 5;
    if (warp >= N) return;
    int v = warp;
    int o = g_off[v];
    int deg = g_off[v + 1] - o;
    int total = deg + 1;                    // + self loop

    int grp = lane >> 3;                    // 0..3: edge offset within iter
    int fl = (lane & 7) * 8;                // features fl..fl+7
    int head = (lane & 7) >> 1;             // fl/16
    float4 adv = *(const float4*)(ad + v * 4);

    float acc[8] = {};
    float ss = 0.f;

    for (int base = 0; base < total; base += 32) {
        int idx = base + lane;
        int s_pre = (idx < deg) ? g_csr[o + idx] : v;
        // lane-parallel: 4 head coefficients for edge idx (fp32)
        float4 a4 = *(const float4*)(as + s_pre * 4);
        float e0 = a4.x + adv.x; e0 = fmaxf(e0, 0.2f * e0);
        float e1 = a4.y + adv.y; e1 = fmaxf(e1, 0.2f * e1);
        float e2 = a4.z + adv.z; e2 = fmaxf(e2, 0.2f * e2);
        float e3 = a4.w + adv.w; e3 = fmaxf(e3, 0.2f * e3);
        *(float4*)&smw[wl][lane * 4] =
            make_float4(__expf(e0), __expf(e1), __expf(e2), __expf(e3));
        __syncwarp();
        int cnt = min(32, total - base);
        #pragma unroll 2
        for (int j = 0; j < cnt; j += 4) {
            int jj = j + grp;
            bool on = jj < cnt;
            int s = __shfl_sync(FULLMASK, s_pre, on ? jj : 0);
            if (on) {
                float w = smw[wl][jj * 4 + head];
                const float4* hp = (const float4*)(hf + s * 64 + fl);
                float4 f0 = hp[0];
                float4 f1 = hp[1];
                acc[0] += w * f0.x; acc[1] += w * f0.y;
                acc[2] += w * f0.z; acc[3] += w * f0.w;
                acc[4] += w * f1.x; acc[5] += w * f1.y;
                acc[6] += w * f1.z; acc[7] += w * f1.w;
                ss += w;
            }
        }
        __syncwarp();
    }

    // combine 4 group partials: lanes {l, l+8, l+16, l+24} share features
    #pragma unroll
    for (int k = 0; k < 8; k++) {
        acc[k] += __shfl_xor_sync(FULLMASK, acc[k], 8);
        acc[k] += __shfl_xor_sync(FULLMASK, acc[k], 16);
    }
    ss += __shfl_xor_sync(FULLMASK, ss, 8);
    ss += __shfl_xor_sync(FULLMASK, ss, 16);

    if (lane < 8) {
        float inv = 1.f / (ss + 1e-16f);
        float4 b0 = *(const float4*)(bias + fl);
        float4 b1 = *(const float4*)(bias + fl + 4);
        float r[8];
        r[0] = acc[0] * inv + b0.x; r[1] = acc[1] * inv + b0.y;
        r[2] = acc[2] * inv + b0.z; r[3] = acc[3] * inv + b0.w;
        r[4] = acc[4] * inv + b1.x; r[5] = acc[5] * inv + b1.y;
        r[6] = acc[6] * inv + b1.z; r[7] = acc[7] * inv + b1.w;
        #pragma unroll
        for (int k = 0; k < 8; k++)
            r[k] = (r[k] > 0.f) ? r[k] : (__expf(r[k]) - 1.f);
        float4* o4 = (float4*)(out + v * 64 + fl);
        o4[0] = make_float4(r[0], r[1], r[2], r[3]);
        o4[1] = make_float4(r[4], r[5], r[6], r[7]);
    }
}

// ---------------- layer-2 aggregate: H=1, C=40, fp16 gather, +bias -----------
// 6 edges per warp-iteration: group g=lane/5 (lanes 30,31 idle) owns edge j+g;
// each active lane loads 8 halves. 6-way group combine at the end.
__global__ void gat_agg2(const __half* __restrict__ hf,
                         const float* __restrict__ as,
                         const float* __restrict__ ad,
                         const float* __restrict__ bias,
                         float* __restrict__ out, int N) {
    int warp = (blockIdx.x * blockDim.x + threadIdx.x) >> 5;
    int lane = threadIdx.x & 31;
    if (warp >= N) return;
    int v = warp;
    int o = g_off[v];
    int deg = g_off[v + 1] - o;
    int total = deg + 1;

    int grp = lane / 5;                     // 0..5 active, 6 for lanes 30,31
    int fl = (lane - grp * 5) * 8;          // features fl..fl+7 (0..32)
    bool lact = lane < 30;
    float adv = ad[v];

    float acc[8] = {};
    float ss = 0.f;

    for (int base = 0; base < total; base += 32) {
        int idx = base + lane;
        int s_pre = (idx < deg) ? g_csr[o + idx] : v;
        float e = __ldg(&as[s_pre]) + adv;
        e = fmaxf(e, 0.2f * e);
        float w_pre = __expf(e);
        int cnt = min(32, total - base);
        #pragma unroll 2
        for (int j = 0; j < cnt; j += 6) {
            int jj = j + grp;
            bool on = lact && (jj < cnt);
            int src = on ? jj : 0;
            int s   = __shfl_sync(FULLMASK, s_pre, src);
            float w = __shfl_sync(FULLMASK, w_pre, src);
            if (on) {
                uint4 raw = *(const uint4*)(hf + s * 40 + fl);   // 8 halves
                const __half2* hp = (const __half2*)&raw;
                float2 f0 = __half22float2(hp[0]);
                float2 f1 = __half22float2(hp[1]);
                float2 f2 = __half22float2(hp[2]);
                float2 f3 = __half22float2(hp[3]);
                acc[0] += w * f0.x; acc[1] += w * f0.y;
                acc[2] += w * f1.x; acc[3] += w * f1.y;
                acc[4] += w * f2.x; acc[5] += w * f2.y;
                acc[6] += w * f3.x; acc[7] += w * f3.y;
                ss += w;
            }
        }
    }

    // combine 6 group partials: lanes {l, l+5, l+10, l+15, l+20, l+25}
    #pragma unroll
    for (int k = 0; k < 8; k++) {
        acc[k] += __shfl_sync(FULLMASK, acc[k], lane + 15);
        float t5  = __shfl_sync(FULLMASK, acc[k], lane + 5);
        float t10 = __shfl_sync(FULLMASK, acc[k], lane + 10);
        acc[k] += t5 + t10;
    }
    {
        ss += __shfl_sync(FULLMASK, ss, lane + 15);
        float t5  = __shfl_sync(FULLMASK, ss, lane + 5);
        float t10 = __shfl_sync(FULLMASK, ss, lane + 10);
        ss += t5 + t10;
    }

    if (lane < 5) {
        float inv = 1.f / (ss + 1e-16f);
        float4 b0 = *(const float4*)(bias + fl);
        float4 b1 = *(const float4*)(bias + fl + 4);
        float4* o4 = (float4*)(out + v * 40 + fl);
        o4[0] = make_float4(acc[0] * inv + b0.x, acc[1] * inv + b0.y,
                            acc[2] * inv + b0.z, acc[3] * inv + b0.w);
        o4[1] = make_float4(acc[4] * inv + b1.x, acc[5] * inv + b1.y,
                            acc[6] * inv + b1.z, acc[7] * inv + b1.w);
    }
}

// ---------------- launch -----------------------------------------------------
extern "C" void kernel_launch(void* const* d_in, const int* in_sizes, int n_in,
                              void* d_out, int out_size) {
    const float* x     = (const float*)d_in[0];
    const int*   ei    = (const int*)d_in[1];       // int32 (JAX default x64-off)
    const float* W1    = (const float*)d_in[2];
    const float* asrc1 = (const float*)d_in[3];
    const float* adst1 = (const float*)d_in[4];
    const float* b1    = (const float*)d_in[5];
    const float* W2    = (const float*)d_in[6];
    const float* asrc2 = (const float*)d_in[7];
    const float* adst2 = (const float*)d_in[8];
    const float* b2    = (const float*)d_in[9];
    float*       out   = (float*)d_out;

    int N = in_sizes[0] / 128;
    int E = in_sizes[1] / 2;
    int nbs = (N + 255) / 256;          // scan blocks (<=196)
    int G1 = (N + 63) / 64;             // gemm1 blocks
    int CB = 1184 - G1;                 // count blocks: exactly one wave
    if (CB < 64) CB = 64;

    float* h1;   cudaGetSymbolAddress((void**)&h1, g_h1);
    float* act1; cudaGetSymbolAddress((void**)&act1, g_act1);
    __half* h2;  cudaGetSymbolAddress((void**)&h2, g_h2);
    float* as1;  cudaGetSymbolAddress((void**)&as1, g_as1);
    float* ad1;  cudaGetSymbolAddress((void**)&ad1, g_ad1);
    float* as2;  cudaGetSymbolAddress((void**)&as2, g_as2);
    float* ad2;  cudaGetSymbolAddress((void**)&ad2, g_ad2);
    int* degp;   cudaGetSymbolAddress((void**)&degp, g_deg);
    int* flagp;  cudaGetSymbolAddress((void**)&flagp, (const void*)g_flag);

    // 1. zero degrees + lookback flags (memsets: no kernel-launch tail)
    cudaMemsetAsync(degp, 0, N * sizeof(int));
    cudaMemsetAsync(flagp, 0, nbs * sizeof(int));
    // 2. GEMM1 (+coef1) overlapped with degree count + rank
    gemm1_count_kernel<<<G1 + CB, 256>>>(x, W1, asrc1, adst1, ei, h1, N, E, G1, CB);
    // 3. single-kernel scan (offsets)
    scan_kernel_lb<<<nbs, 256>>>(N, E);
    // 4. atomic-free CSR scatter
    scatter_kernel<<<(E + 2047) / 2048, 256>>>(ei, E, N);
    // 5. layer-1 aggregate (+bias+ELU), 128-thread blocks (less tail imbalance)
    gat_agg1<<<(N * 32 + 127) / 128, 128>>>(h1, as1, ad1, b1, act1, N);
    // 6. GEMM2 (+coef2, half h2)
    gemm2_kernel<<<(N + 63) / 64, 128>>>(act1, W2, asrc2, adst2, h2, N);
    // 7. layer-2 aggregate (+bias)
    gat_agg2<<<(N * 32 + 127) / 128, 128>>>(h2, as2, ad2, b2, out, N);
}

// round 16
// speedup vs baseline: 1.4302x; 1.4302x over previous
#include <cuda_runtime.h>
#include <cuda_fp16.h>

#define FULLMASK 0xffffffffu

constexpr int MAXN = 50016;
constexpr int MAXE = 1000000;
constexpr int MAXB = 256;          // max scan blocks (N/256)

// ---------------- scratch (static device memory: allocation-free) -------------
__device__ __half g_h1[MAXN * 64];   // layer1 pre-agg features, fp16 (N,4,16)
__device__ float  g_act1[MAXN * 64]; // layer1 output after bias+ELU (fp32)
__device__ __half g_h2[MAXN * 40];   // layer2 pre-agg features, fp16
__device__ float g_as1[MAXN * 4];
__device__ float g_ad1[MAXN * 4];
__device__ float g_as2[MAXN];
__device__ float g_ad2[MAXN];
__device__ float g_w1[MAXE * 4];     // CSR-ordered layer1 softmax weights (4 heads)
__device__ int   g_deg[MAXN];
__device__ int   g_off[MAXN + 1];
__device__ int   g_csr[MAXE];        // source node ids grouped by dst
__device__ int   g_rank[MAXE];       // within-destination rank of each edge
__device__ int           g_partial[MAXB];
__device__ volatile int  g_flag[MAXB];

// ---------------- fused GEMM1 (+coef1 epilogue, half out) || count+rank -------
__global__ void gemm1_count_kernel(const float* __restrict__ x,
                                   const float* __restrict__ W,
                                   const float* __restrict__ a_s,
                                   const float* __restrict__ a_d,
                                   const int* __restrict__ ei,
                                   __half* __restrict__ out,
                                   int N, int E, int G1, int CB) {
    __shared__ float xs[64 * 64];    // 16KB
    __shared__ float Ws[64 * 64];    // 16KB
    int tid = threadIdx.x;

    if ((int)blockIdx.x >= G1) {     // ---- count + rank path (grid-stride) ----
        int stride = CB * 256;
        for (int e = (blockIdx.x - G1) * 256 + tid; e < E; e += stride) {
            int d = __ldg(&ei[E + e]);
            if ((unsigned)d < (unsigned)N)
                g_rank[e] = atomicAdd(&g_deg[d], 1);
        }
        return;
    }

    // ---- gemm path ----
    int base = blockIdx.x * 64;
    int ty = tid >> 4, tx = tid & 15;
    float acc[4][4] = {};
    const float4* xg = (const float4*)x;
    const float4* Wg = (const float4*)W;
    #pragma unroll
    for (int kc = 0; kc < 2; kc++) {
        for (int i = tid; i < 1024; i += 256) {      // 64 rows x 16 float4
            int r = i >> 4, c = i & 15;
            int row = base + r;
            ((float4*)xs)[i] = (row < N) ? xg[row * 32 + kc * 16 + c]
                                         : make_float4(0.f, 0.f, 0.f, 0.f);
        }
        for (int i = tid; i < 1024; i += 256) {
            int r = i >> 4, c = i & 15;
            ((float4*)Ws)[i] = Wg[(kc * 64 + r) * 16 + c];
        }
        __syncthreads();
        #pragma unroll 8
        for (int k = 0; k < 64; k++) {
            float4 wv = ((float4*)Ws)[k * 16 + tx];
            float xv[4];
            #pragma unroll
            for (int i = 0; i < 4; i++) xv[i] = xs[(ty * 4 + i) * 64 + k];
            #pragma unroll
            for (int i = 0; i < 4; i++) {
                acc[i][0] += xv[i] * wv.x;
                acc[i][1] += xv[i] * wv.y;
                acc[i][2] += xv[i] * wv.z;
                acc[i][3] += xv[i] * wv.w;
            }
        }
        __syncthreads();
    }
    #pragma unroll
    for (int i = 0; i < 4; i++) {
        int row = base + ty * 4 + i;
        if (row < N) {
            __half2* o2 = (__half2*)(out + row * 64 + tx * 4);   // 8B aligned
            o2[0] = __floats2half2_rn(acc[i][0], acc[i][1]);
            o2[1] = __floats2half2_rn(acc[i][2], acc[i][3]);
        }
    }

    // ---- coef1 epilogue (fp32): head h = tx>>2 owns cols tx*4..tx*4+3
    float asc[4], adc[4];
    #pragma unroll
    for (int j = 0; j < 4; j++) {
        asc[j] = __ldg(a_s + tx * 4 + j);
        adc[j] = __ldg(a_d + tx * 4 + j);
    }
    int h = tx >> 2;
    #pragma unroll
    for (int i = 0; i < 4; i++) {
        float s1 = acc[i][0] * asc[0] + acc[i][1] * asc[1]
                 + acc[i][2] * asc[2] + acc[i][3] * asc[3];
        float s2 = acc[i][0] * adc[0] + acc[i][1] * adc[1]
                 + acc[i][2] * adc[2] + acc[i][3] * adc[3];
        s1 += __shfl_xor_sync(FULLMASK, s1, 1);
        s1 += __shfl_xor_sync(FULLMASK, s1, 2);
        s2 += __shfl_xor_sync(FULLMASK, s2, 1);
        s2 += __shfl_xor_sync(FULLMASK, s2, 2);
        int row = base + ty * 4 + i;
        if ((tx & 3) == 0 && row < N) {
            g_as1[row * 4 + h] = s1;
            g_ad1[row * 4 + h] = s2;
        }
    }
}

// ---------------- single-kernel decoupled-lookback scan ----------------------
__global__ void scan_kernel_lb(int N, int E) {
    int b = blockIdx.x, tid = threadIdx.x, lane = tid & 31, wid = tid >> 5;
    int i = b * 256 + tid;
    int x = (i < N) ? g_deg[i] : 0;
    int v = x;
    #pragma unroll
    for (int d = 1; d < 32; d <<= 1) {
        int t = __shfl_up_sync(FULLMASK, v, d);
        if (lane >= d) v += t;
    }
    __shared__ int ws[8];
    __shared__ int s_prev;
    if (lane == 31) ws[wid] = v;
    if (tid == 0) s_prev = 0;
    __syncthreads();
    if (tid < 8) {
        int wv = ws[tid];
        #pragma unroll
        for (int d = 1; d < 8; d <<= 1) {
            int t = __shfl_up_sync(0xffu, wv, d);
            if (tid >= d) wv += t;
        }
        ws[tid] = wv;   // inclusive warp totals
    }
    __syncthreads();
    int incl = v + ((wid == 0) ? 0 : ws[wid - 1]);
    if (tid == 0) {
        g_partial[b] = ws[7];
        __threadfence();
        g_flag[b] = 1;
    }
    if (tid < b) {
        while (g_flag[tid] == 0) { }
        __threadfence();
        atomicAdd(&s_prev, g_partial[tid]);
    }
    __syncthreads();
    int excl = s_prev + incl - x;
    if (i < N) g_off[i] = excl;
    if (b == 0 && tid == 0) g_off[N] = E;
}

// ---------------- scatter + layer1 weight precompute (CSR order) -------------
// Atomic-free placement via precomputed rank; additionally computes the 4 head
// softmax weights for each edge and stores them at the edge's CSR position.
// Scatter was latency-bound (issue 7%), so the extra gathers hide in idle slots.
__global__ void scatter_kernel(const int* __restrict__ ei, int E, int N) {
    int b0 = blockIdx.x * 2048;
    #pragma unroll
    for (int k = 0; k < 8; k++) {
        int e = b0 + k * 256 + threadIdx.x;
        if (e < E) {
            int s = __ldg(&ei[e]);
            int d = __ldg(&ei[E + e]);
            if ((unsigned)s < (unsigned)N && (unsigned)d < (unsigned)N) {
                int p = __ldg(&g_off[d]) + g_rank[e];
                g_csr[p] = s;
                float4 a4 = *(const float4*)(g_as1 + s * 4);
                float4 b4 = *(const float4*)(g_ad1 + d * 4);
                float e0 = a4.x + b4.x; e0 = fmaxf(e0, 0.2f * e0);
                float e1 = a4.y + b4.y; e1 = fmaxf(e1, 0.2f * e1);
                float e2 = a4.z + b4.z; e2 = fmaxf(e2, 0.2f * e2);
                float e3 = a4.w + b4.w; e3 = fmaxf(e3, 0.2f * e3);
                *(float4*)(g_w1 + p * 4) =
                    make_float4(__expf(e0), __expf(e1), __expf(e2), __expf(e3));
            }
        }
    }
}

// ---------------- GEMM 2 (+coef2 epilogue): act1[N,64]@W2[64,40], half out ---
__global__ void gemm2_kernel(const float* __restrict__ x, const float* __restrict__ W,
                             const float* __restrict__ a_s, const float* __restrict__ a_d,
                             __half* __restrict__ out, int N) {
    __shared__ float xs[64 * 64];    // 16KB
    __shared__ float Ws[64 * 40];    // 10KB
    int tid = threadIdx.x;
    int base = blockIdx.x * 64;
    const float4* xg = (const float4*)x;
    for (int i = tid; i < 1024; i += 128) {
        int r = i >> 4, c = i & 15;
        int row = base + r;
        ((float4*)xs)[i] = (row < N) ? xg[row * 16 + c]
                                     : make_float4(0.f, 0.f, 0.f, 0.f);
    }
    for (int i = tid; i < 640; i += 128)
        ((float4*)Ws)[i] = ((const float4*)W)[i];
    __syncthreads();
    int ty = tid >> 3, tx = tid & 7;                 // 16 row-groups x 8 col-groups
    int c0 = tx * 5;
    float acc[4][5] = {};
    #pragma unroll 4
    for (int k = 0; k < 64; k++) {
        float wv[5];
        #pragma unroll
        for (int j = 0; j < 5; j++) wv[j] = Ws[k * 40 + c0 + j];
        #pragma unroll
        for (int i = 0; i < 4; i++) {
            float xv = xs[(ty * 4 + i) * 64 + k];
            #pragma unroll
            for (int j = 0; j < 5; j++) acc[i][j] += xv * wv[j];
        }
    }
    float asc[5], adc[5];
    #pragma unroll
    for (int j = 0; j < 5; j++) {
        asc[j] = __ldg(a_s + c0 + j);
        adc[j] = __ldg(a_d + c0 + j);
    }
    #pragma unroll
    for (int i = 0; i < 4; i++) {
        int row = base + ty * 4 + i;
        if (row < N) {
            #pragma unroll
            for (int j = 0; j < 5; j++)
                out[row * 40 + c0 + j] = __float2half_rn(acc[i][j]);
        }
        float s1 = 0.f, s2 = 0.f;
        #pragma unroll
        for (int j = 0; j < 5; j++) { s1 += acc[i][j] * asc[j]; s2 += acc[i][j] * adc[j]; }
        #pragma unroll
        for (int d = 1; d < 8; d <<= 1) {
            s1 += __shfl_xor_sync(FULLMASK, s1, d);
            s2 += __shfl_xor_sync(FULLMASK, s2, d);
        }
        if (tx == 0 && row < N) { g_as2[row] = s1; g_ad2[row] = s2; }
    }
}

// ---------------- layer-1 aggregate: H=4, C=16, fp16 gather, +bias+ELU -------
// Chunk stage now only stages 32 precomputed weight-quads (coalesced LDG.128
// + STS.128) — no random coef gather, no exp. Inner loop unchanged from R14:
// 4 edges/iter, 8 lanes/edge, 1 LDG.128 of 8 halves per lane. Self-loop is
// folded in once at the end.
__global__ void gat_agg1(const __half* __restrict__ hf,
                         const float* __restrict__ as,
                         const float* __restrict__ ad,
                         const float* __restrict__ bias,
                         float* __restrict__ out, int N) {
    __shared__ float smw[8][128];           // 8 warps x 32 edges x 4 heads
    int warp = (blockIdx.x * blockDim.x + threadIdx.x) >> 5;
    int lane = threadIdx.x & 31;
    int wl = threadIdx.x >> 5;
    if (warp >= N) return;
    int v = warp;
    int o = g_off[v];
    int deg = g_off[v + 1] - o;

    int grp = lane >> 3;                    // 0..3: edge offset within iter
    int fl = (lane & 7) * 8;                // features fl..fl+7
    int head = (lane & 7) >> 1;             // fl/16

    float acc[8] = {};
    float ss = 0.f;

    for (int base = 0; base < deg; base += 32) {
        int idx = base + lane;
        bool he = idx < deg;
        int s_pre = he ? g_csr[o + idx] : 0;
        float4 w4 = he ? *(const float4*)(g_w1 + (o + idx) * 4)
                       : make_float4(0.f, 0.f, 0.f, 0.f);
        *(float4*)&smw[wl][lane * 4] = w4;
        __syncwarp();
        int cnt = min(32, deg - base);
        #pragma unroll 2
        for (int j = 0; j < cnt; j += 4) {
            int jj = j + grp;
            bool on = jj < cnt;
            int s = __shfl_sync(FULLMASK, s_pre, on ? jj : 0);
            if (on) {
                float w = smw[wl][jj * 4 + head];
                uint4 raw = *(const uint4*)(hf + s * 64 + fl);   // 8 halves
                const __half2* hp = (const __half2*)&raw;
                float2 f0 = __half22float2(hp[0]);
                float2 f1 = __half22float2(hp[1]);
                float2 f2 = __half22float2(hp[2]);
                float2 f3 = __half22float2(hp[3]);
                acc[0] += w * f0.x; acc[1] += w * f0.y;
                acc[2] += w * f1.x; acc[3] += w * f1.y;
                acc[4] += w * f2.x; acc[5] += w * f2.y;
                acc[6] += w * f3.x; acc[7] += w * f3.y;
                ss += w;
            }
        }
        __syncwarp();
    }

    // self loop: weight from own coefs, features from own row
    {
        float4 a4 = *(const float4*)(as + v * 4);
        float4 b4 = *(const float4*)(ad + v * 4);
        float e0 = (head == 0) ? (a4.x + b4.x) : (head == 1) ? (a4.y + b4.y)
                 : (head == 2) ? (a4.z + b4.z) : (a4.w + b4.w);
        e0 = fmaxf(e0, 0.2f * e0);
        float w = __expf(e0);
        uint4 raw = *(const uint4*)(hf + v * 64 + fl);
        const __half2* hp = (const __half2*)&raw;
        float2 f0 = __half22float2(hp[0]);
        float2 f1 = __half22float2(hp[1]);
        float2 f2 = __half22float2(hp[2]);
        float2 f3 = __half22float2(hp[3]);
        // fold into group 0's partial only (grp==0 lanes own jj pattern 0 mod 4,
        // but every lane holds a full feature slice: add once per lane-column).
        if (grp == 0) {
            acc[0] += w * f0.x; acc[1] += w * f0.y;
            acc[2] += w * f1.x; acc[3] += w * f1.y;
            acc[4] += w * f2.x; acc[5] += w * f2.y;
            acc[6] += w * f3.x; acc[7] += w * f3.y;
            ss += w;
        }
    }

    // combine 4 group partials: lanes {l, l+8, l+16, l+24} share features
    #pragma unroll
    for (int k = 0; k < 8; k++) {
        acc[k] += __shfl_xor_sync(FULLMASK, acc[k], 8);
        acc[k] += __shfl_xor_sync(FULLMASK, acc[k], 16);
    }
    ss += __shfl_xor_sync(FULLMASK, ss, 8);
    ss += __shfl_xor_sync(FULLMASK, ss, 16);

    if (lane < 8) {
        float inv = 1.f / (ss + 1e-16f);
        float4 b0 = *(const float4*)(bias + fl);
        float4 b1 = *(const float4*)(bias + fl + 4);
        float r[8];
        r[0] = acc[0] * inv + b0.x; r[1] = acc[1] * inv + b0.y;
        r[2] = acc[2] * inv + b0.z; r[3] = acc[3] * inv + b0.w;
        r[4] = acc[4] * inv + b1.x; r[5] = acc[5] * inv + b1.y;
        r[6] = acc[6] * inv + b1.z; r[7] = acc[7] * inv + b1.w;
        #pragma unroll
        for (int k = 0; k < 8; k++)
            r[k] = (r[k] > 0.f) ? r[k] : (__expf(r[k]) - 1.f);
        float4* o4 = (float4*)(out + v * 64 + fl);
        o4[0] = make_float4(r[0], r[1], r[2], r[3]);
        o4[1] = make_float4(r[4], r[5], r[6], r[7]);
    }
}

// ---------------- layer-2 aggregate: H=1, C=40, fp16 gather, +bias -----------
// 6 edges per warp-iteration: group g=lane/5 (lanes 30,31 idle) owns edge j+g;
// each active lane loads 8 halves. 6-way group combine at the end. (R14 form.)
__global__ void gat_agg2(const __half* __restrict__ hf,
                         const float* __restrict__ as,
                         const float* __restrict__ ad,
                         const float* __restrict__ bias,
                         float* __restrict__ out, int N) {
    int warp = (blockIdx.x * blockDim.x + threadIdx.x) >> 5;
    int lane = threadIdx.x & 31;
    if (warp >= N) return;
    int v = warp;
    int o = g_off[v];
    int deg = g_off[v + 1] - o;
    int total = deg + 1;

    int grp = lane / 5;                     // 0..5 active, 6 for lanes 30,31
    int fl = (lane - grp * 5) * 8;          // features fl..fl+7 (0..32)
    bool lact = lane < 30;
    float adv = ad[v];

    float acc[8] = {};
    float ss = 0.f;

    for (int base = 0; base < total; base += 32) {
        int idx = base + lane;
        int s_pre = (idx < deg) ? g_csr[o + idx] : v;
        float e = __ldg(&as[s_pre]) + adv;
        e = fmaxf(e, 0.2f * e);
        float w_pre = __expf(e);
        int cnt = min(32, total - base);
        #pragma unroll 2
        for (int j = 0; j < cnt; j += 6) {
            int jj = j + grp;
            bool on = lact && (jj < cnt);
            int src = on ? jj : 0;
            int s   = __shfl_sync(FULLMASK, s_pre, src);
            float w = __shfl_sync(FULLMASK, w_pre, src);
            if (on) {
                uint4 raw = *(const uint4*)(hf + s * 40 + fl);   // 8 halves
                const __half2* hp = (const __half2*)&raw;
                float2 f0 = __half22float2(hp[0]);
                float2 f1 = __half22float2(hp[1]);
                float2 f2 = __half22float2(hp[2]);
                float2 f3 = __half22float2(hp[3]);
                acc[0] += w * f0.x; acc[1] += w * f0.y;
                acc[2] += w * f1.x; acc[3] += w * f1.y;
                acc[4] += w * f2.x; acc[5] += w * f2.y;
                acc[6] += w * f3.x; acc[7] += w * f3.y;
                ss += w;
            }
        }
    }

    // combine 6 group partials: lanes {l, l+5, l+10, l+15, l+20, l+25}
    #pragma unroll
    for (int k = 0; k < 8; k++) {
        acc[k] += __shfl_sync(FULLMASK, acc[k], lane + 15);
        float t5  = __shfl_sync(FULLMASK, acc[k], lane + 5);
        float t10 = __shfl_sync(FULLMASK, acc[k], lane + 10);
        acc[k] += t5 + t10;
    }
    {
        ss += __shfl_sync(FULLMASK, ss, lane + 15);
        float t5  = __shfl_sync(FULLMASK, ss, lane + 5);
        float t10 = __shfl_sync(FULLMASK, ss, lane + 10);
        ss += t5 + t10;
    }

    if (lane < 5) {
        float inv = 1.f / (ss + 1e-16f);
        float4 b0 = *(const float4*)(bias + fl);
        float4 b1 = *(const float4*)(bias + fl + 4);
        float4* o4 = (float4*)(out + v * 40 + fl);
        o4[0] = make_float4(acc[0] * inv + b0.x, acc[1] * inv + b0.y,
                            acc[2] * inv + b0.z, acc[3] * inv + b0.w);
        o4[1] = make_float4(acc[4] * inv + b1.x, acc[5] * inv + b1.y,
                            acc[6] * inv + b1.z, acc[7] * inv + b1.w);
    }
}

// ---------------- launch -----------------------------------------------------
extern "C" void kernel_launch(void* const* d_in, const int* in_sizes, int n_in,
                              void* d_out, int out_size) {
    const float* x     = (const float*)d_in[0];
    const int*   ei    = (const int*)d_in[1];       // int32 (JAX default x64-off)
    const float* W1    = (const float*)d_in[2];
    const float* asrc1 = (const float*)d_in[3];
    const float* adst1 = (const float*)d_in[4];
    const float* b1    = (const float*)d_in[5];
    const float* W2    = (const float*)d_in[6];
    const float* asrc2 = (const float*)d_in[7];
    const float* adst2 = (const float*)d_in[8];
    const float* b2    = (const float*)d_in[9];
    float*       out   = (float*)d_out;

    int N = in_sizes[0] / 128;
    int E = in_sizes[1] / 2;
    int nbs = (N + 255) / 256;          // scan blocks (<=196)
    int G1 = (N + 63) / 64;             // gemm1 blocks
    int CB = 1184 - G1;                 // count blocks: exactly one wave
    if (CB < 64) CB = 64;

    __half* h1;  cudaGetSymbolAddress((void**)&h1, g_h1);
    float* act1; cudaGetSymbolAddress((void**)&act1, g_act1);
    __half* h2;  cudaGetSymbolAddress((void**)&h2, g_h2);
    float* as1;  cudaGetSymbolAddress((void**)&as1, g_as1);
    float* ad1;  cudaGetSymbolAddress((void**)&ad1, g_ad1);
    float* as2;  cudaGetSymbolAddress((void**)&as2, g_as2);
    float* ad2;  cudaGetSymbolAddress((void**)&ad2, g_ad2);
    int* degp;   cudaGetSymbolAddress((void**)&degp, g_deg);
    int* flagp;  cudaGetSymbolAddress((void**)&flagp, (const void*)g_flag);

    // 1. zero degrees + lookback flags (memsets: no kernel-launch tail)
    cudaMemsetAsync(degp, 0, N * sizeof(int));
    cudaMemsetAsync(flagp, 0, nbs * sizeof(int));
    // 2. GEMM1 (+coef1, half h1) overlapped with degree count + rank
    gemm1_count_kernel<<<G1 + CB, 256>>>(x, W1, asrc1, adst1, ei, h1, N, E, G1, CB);
    // 3. single-kernel scan (offsets)
    scan_kernel_lb<<<nbs, 256>>>(N, E);
    // 4. CSR scatter + layer1 weight precompute
    scatter_kernel<<<(E + 2047) / 2048, 256>>>(ei, E, N);
    // 5. layer-1 aggregate (+bias+ELU)
    gat_agg1<<<(N * 32 + 255) / 256, 256>>>(h1, as1, ad1, b1, act1, N);
    // 6. GEMM2 (+coef2, half h2)
    gemm2_kernel<<<(N + 63) / 64, 128>>>(act1, W2, asrc2, adst2, h2, N);
    // 7. layer-2 aggregate (+bias)
    gat_agg2<<<(N * 32 + 255) / 256, 256>>>(h2, as2, ad2, b2, out, N);
}